// round 14
// baseline (speedup 1.0000x reference)
#include <cuda_runtime.h>
#include <cuda_bf16.h>
#include <math.h>
#include <stdint.h>

#define T_STEPS 4096
#define HS 512
#define INSZ 2048
#define MBK 100
#define NCTA 128
#define NTHR 512

// ---------------- device scratch (allocations are forbidden) ----------------
__device__ float g_pre_rha[T_STEPS * HS];
__device__ float g_pre_rhm[T_STEPS * HS];
__device__ float g_pre_ca [T_STEPS * HS];
__device__ float g_pre_cm [T_STEPS * HS];
__device__ float g_pre_wpa[T_STEPS * MBK];
__device__ float g_pre_wpm[T_STEPS * MBK];
__device__ float g_state[2][3 * HS];       // double-buffered: [ha | hm | h]
__device__ unsigned long long g_rt[HS];    // tagged r: (epoch<<32)|bits(float)
// logit accumulators, TRIPLE buffered: [0..99]=ar, [100..102]=aw,
// [103..202]=aw_a(ha part), [203..302]=aw_m(hm part)
__device__ float g_acc[3][320];
__device__ unsigned int g_bar;

__device__ __forceinline__ float warpsum(float v) {
#pragma unroll
    for (int o = 16; o; o >>= 1) v += __shfl_xor_sync(0xFFFFFFFFu, v, o);
    return v;
}

__device__ __forceinline__ unsigned int ld_acq(const unsigned int* p) {
    unsigned int v;
    asm volatile("ld.global.acquire.gpu.u32 %0, [%1];" : "=r"(v) : "l"(p));
    return v;
}
__device__ __forceinline__ unsigned long long ldcg_u64(const unsigned long long* p) {
    unsigned long long v;
    asm volatile("ld.global.cg.u64 %0, [%1];" : "=l"(v) : "l"(p));
    return v;
}
__device__ __forceinline__ void stcg_u64(unsigned long long* p, unsigned long long v) {
    asm volatile("st.global.cg.u64 [%0], %1;" :: "l"(p), "l"(v));
}

// arrive: release-atomic (CTA __syncthreads first so the release publishes all
// of this CTA's prior global stores at gpu scope)
__device__ __forceinline__ void gbar_arrive() {
    __syncthreads();
    if (threadIdx.x == 0)
        asm volatile("red.release.gpu.global.add.u32 [%0], 1;" :: "l"(&g_bar) : "memory");
}
// wait: warp 15 polls global with acquire, publishes epoch to SMEM; others spin SMEM.
__device__ __forceinline__ void gbar_wait(unsigned int target, volatile unsigned int* epoch) {
    const int warp = threadIdx.x >> 5, lane = threadIdx.x & 31;
    if (warp == 15) {
        if (lane == 0) {
            while (ld_acq(&g_bar) < target) {}
            *epoch = target;
        }
        __syncwarp();
    } else {
        if (lane == 0) { while (*epoch < target) {} }
        __syncwarp();
    }
}

__global__ void reset_kernel() {
    int i = blockIdx.x * blockDim.x + threadIdx.x;
    if (i == 0) g_bar = 0u;
    if (i < 3 * 320) (&g_acc[0][0])[i] = 0.f;
    if (i < 2 * 3 * HS) (&g_state[0][0])[i] = 0.f;
    if (i < HS) g_rt[i] = 0ull;
}

// =====================================================================
// Precompute GEMMs: C[4096,N] = X @ W[rowOff:+2048, :N] + bias (6 jobs in z)
// =====================================================================
__global__ __launch_bounds__(256)
void gemm6_kernel(const float* __restrict__ Xa, const float* __restrict__ Xm,
                  const float* __restrict__ W_rha, const float* __restrict__ b_rha,
                  const float* __restrict__ W_rhm, const float* __restrict__ b_rhm,
                  const float* __restrict__ W_ca,  const float* __restrict__ b_ca,
                  const float* __restrict__ W_cm,  const float* __restrict__ b_cm,
                  const float* __restrict__ W_wpa, const float* __restrict__ b_wpa,
                  const float* __restrict__ W_wpm, const float* __restrict__ b_wpm)
{
    const float* A; const float* B; const float* bias; float* C; int N; int rowOff;
    switch (blockIdx.z) {
        case 0: A = Xa; B = W_rha; bias = b_rha; C = g_pre_rha; N = HS;  rowOff = 0;   break;
        case 1: A = Xm; B = W_rhm; bias = b_rhm; C = g_pre_rhm; N = HS;  rowOff = 0;   break;
        case 2: A = Xa; B = W_ca;  bias = b_ca;  C = g_pre_ca;  N = HS;  rowOff = HS;  break;
        case 3: A = Xm; B = W_cm;  bias = b_cm;  C = g_pre_cm;  N = HS;  rowOff = HS;  break;
        case 4: A = Xa; B = W_wpa; bias = b_wpa; C = g_pre_wpa; N = MBK; rowOff = HS;  break;
        default:A = Xm; B = W_wpm; bias = b_wpm; C = g_pre_wpm; N = MBK; rowOff = HS;  break;
    }
    if ((int)blockIdx.x * 128 >= N) return;

    const int K = INSZ;
    __shared__ float As[8][128];
    __shared__ float Bs[8][128];
    const int tid  = threadIdx.x;
    const int tx   = tid & 15, ty = tid >> 4;
    const int brow = blockIdx.y, bcol = blockIdx.x;

    const int arow = tid >> 1, akq = (tid & 1) * 4;
    const float* Ag = A + (size_t)(brow * 128 + arow) * K + akq;
    const int bk = tid >> 5, bc = (tid & 31) * 4;
    const int gcol = bcol * 128 + bc;
    const bool bok = (gcol + 3 < N);

    float acc[8][8];
#pragma unroll
    for (int i = 0; i < 8; i++)
#pragma unroll
        for (int j = 0; j < 8; j++) acc[i][j] = 0.f;

    for (int k0 = 0; k0 < K; k0 += 8) {
        float4 av = *(const float4*)(Ag + k0);
        As[akq + 0][arow] = av.x; As[akq + 1][arow] = av.y;
        As[akq + 2][arow] = av.z; As[akq + 3][arow] = av.w;
        float4 bv = bok ? *(const float4*)(B + (size_t)(rowOff + k0 + bk) * N + gcol)
                        : make_float4(0.f, 0.f, 0.f, 0.f);
        *(float4*)&Bs[bk][bc] = bv;
        __syncthreads();
#pragma unroll
        for (int kk = 0; kk < 8; ++kk) {
            float ra[8], rb[8];
            *(float4*)(ra)     = *(const float4*)&As[kk][ty * 4];
            *(float4*)(ra + 4) = *(const float4*)&As[kk][64 + ty * 4];
            *(float4*)(rb)     = *(const float4*)&Bs[kk][tx * 4];
            *(float4*)(rb + 4) = *(const float4*)&Bs[kk][64 + tx * 4];
#pragma unroll
            for (int i = 0; i < 8; i++)
#pragma unroll
                for (int j = 0; j < 8; j++) acc[i][j] = fmaf(ra[i], rb[j], acc[i][j]);
        }
        __syncthreads();
    }
#pragma unroll
    for (int i = 0; i < 8; i++) {
        int row = brow * 128 + ((i < 4) ? (ty * 4 + i) : (64 + ty * 4 + i - 4));
#pragma unroll
        for (int j = 0; j < 8; j++) {
            int col = bcol * 128 + ((j < 4) ? (tx * 4 + j) : (64 + tx * 4 + j - 4));
            if (col < N) C[(size_t)row * N + col] = acc[i][j] + bias[col];
        }
    }
}

// =====================================================================
// Persistent sequential kernel: 128 CTAs x 512 threads, each owns 4 HS columns.
// ONE global barrier per step; r flows through tagged 8B words.
// =====================================================================
struct SeqSmem {
    float wrh [4][1024];   // W_rh  col slices: rows [r(512) | h(512)]
    float wrha[4][1024];   // W_rha rows 2048..3071: [r | ha]
    float wrhm[4][1024];   // W_rhm rows 2048..3071: [r | hm]
    float wca [4][512];    // W_ca rows 0..511 (ha)
    float wcm [4][512];    // W_cm rows 0..511 (hm)
    float wrp_r [12][104]; // W_rp rows owned x 100 logits
    float wwp_r [12][4];   // W_wp rows owned x 3
    float wwpa_r[4][104];  // W_wpa rows c4..+3 (ha part) x 100
    float wwpm_r[4][104];
    float mem [2][4][MBK]; // DOUBLE-buffered mem[:, owned cols], col-major
    float sx  [1536];      // state staged for x-part dots
    float par [MBK], pawa[MBK], pawm[MBK], aw[3];
    float snew[12];        // new state own comps: [ha1(4) | hm1(4) | h1(4)]
    float ca_own[4], cm_own[4];
    float pre_rha[4], pre_rhm[4];
    float brh[4];
    float brp_s[MBK], bwp_s[3];
    unsigned int epoch;
};

__global__ __launch_bounds__(NTHR, 1)
void seq_kernel(const float* __restrict__ W_ca,  const float* __restrict__ W_cm,
                const float* __restrict__ W_wp,  const float* __restrict__ b_wp,
                const float* __restrict__ W_wpa, const float* __restrict__ W_wpm,
                const float* __restrict__ W_rp,  const float* __restrict__ b_rp,
                const float* __restrict__ W_rh,  const float* __restrict__ b_rh,
                const float* __restrict__ W_rha, const float* __restrict__ W_rhm,
                float* __restrict__ out)
{
    extern __shared__ float smem_raw[];
    SeqSmem& s = *reinterpret_cast<SeqSmem*>(smem_raw);
    const int tid  = threadIdx.x;
    const int warp = tid >> 5, lane = tid & 31;
    const int cta  = blockIdx.x;
    const int c4   = cta * 4;

    // ---- one-time weight load ----
    for (int idx = tid; idx < 4 * 1024; idx += NTHR) {
        int col = idx & 3, i = idx >> 2;
        s.wrh [col][i] = __ldg(&W_rh [(size_t)i * HS + c4 + col]);
        s.wrha[col][i] = __ldg(&W_rha[(size_t)(INSZ + i) * HS + c4 + col]);
        s.wrhm[col][i] = __ldg(&W_rhm[(size_t)(INSZ + i) * HS + c4 + col]);
    }
    for (int idx = tid; idx < 4 * 512; idx += NTHR) {
        int col = idx & 3, i = idx >> 2;
        s.wca[col][i] = __ldg(&W_ca[(size_t)i * HS + c4 + col]);
        s.wcm[col][i] = __ldg(&W_cm[(size_t)i * HS + c4 + col]);
    }
    for (int idx = tid; idx < 12 * MBK; idx += NTHR) {
        int k = idx / MBK, j = idx % MBK;
        int row = (k < 4) ? (c4 + k) : (k < 8) ? (512 + c4 + k - 4) : (1024 + c4 + k - 8);
        s.wrp_r[k][j] = __ldg(&W_rp[(size_t)row * MBK + j]);
    }
    if (tid < 36) {
        int k = tid / 3, j = tid % 3;
        int row = (k < 4) ? (c4 + k) : (k < 8) ? (512 + c4 + k - 4) : (1024 + c4 + k - 8);
        s.wwp_r[k][j] = __ldg(&W_wp[(size_t)row * 3 + j]);
    }
    for (int idx = tid; idx < 4 * MBK; idx += NTHR) {
        int k = idx / MBK, j = idx % MBK;
        s.wwpa_r[k][j] = __ldg(&W_wpa[(size_t)(c4 + k) * MBK + j]);
        s.wwpm_r[k][j] = __ldg(&W_wpm[(size_t)(c4 + k) * MBK + j]);
    }
    for (int i = tid; i < MBK; i += NTHR) s.brp_s[i] = __ldg(&b_rp[i]);
    if (tid < 3) s.bwp_s[tid] = b_wp[tid];
    if (tid < 4) s.brh[tid] = b_rh[c4 + tid];
    for (int idx = tid; idx < 2 * 4 * MBK; idx += NTHR) (&s.mem[0][0][0])[idx] = 0.f;
    if (tid == 0) s.epoch = 0u;
    __syncthreads();

    for (int t = 0; t < T_STEPS; ++t) {
        const int sb  = t & 1;            // state buffer read this step
        const int mb  = t & 1;            // mem buffer read this step
        const int ar3 = t % 3;            // acc buffer read
        const int ap3 = (t + 1) % 3;      // acc buffer pushed (for t+1)
        const int az3 = (t + 2) % 3;      // acc buffer zeroed
        const float* st_rd = g_state[sb];
        float* st_wr = g_state[sb ^ 1];
        const unsigned want = (unsigned)(t + 1);

        // ============ phase A1: c dots / softmaxes / aw / sx staging ============
        if (warp < 8) {
            int col = warp & 3;
            bool isA = warp < 4;
            float pre = 0.f;
            if (lane == 0)
                pre = __ldcg(isA ? &g_pre_ca[(size_t)t * HS + c4 + col]
                                 : &g_pre_cm[(size_t)t * HS + c4 + col]);
            const float* w  = isA ? s.wca[col] : s.wcm[col];
            const float* xg = isA ? st_rd : (st_rd + 512);
            float acc = 0.f;
#pragma unroll
            for (int i = 0; i < 512; i += 32) acc = fmaf(__ldcg(&xg[i + lane]), w[i + lane], acc);
            acc = warpsum(acc);
            if (lane == 0) {
                if (isA) s.ca_own[col] = fmaxf(acc + pre, 0.f);
                else     s.cm_own[col] = fmaxf(acc + pre, 0.f);
            }
        } else if (warp < 11) {
            float v[4];
#pragma unroll
            for (int k = 0; k < 4; k++) {
                int j = lane + 32 * k;
                if (j < MBK) {
                    if (warp == 8)      v[k] = __ldcg(&g_acc[ar3][j]) + s.brp_s[j];
                    else if (warp == 9) v[k] = __ldcg(&g_acc[ar3][103 + j]) + __ldcg(&g_pre_wpa[(size_t)t * MBK + j]);
                    else                v[k] = __ldcg(&g_acc[ar3][203 + j]) + __ldcg(&g_pre_wpm[(size_t)t * MBK + j]);
                } else v[k] = -1e30f;
            }
            float m = fmaxf(fmaxf(v[0], v[1]), fmaxf(v[2], v[3]));
#pragma unroll
            for (int o = 16; o; o >>= 1) m = fmaxf(m, __shfl_xor_sync(0xFFFFFFFFu, m, o));
            float e[4], sum = 0.f;
#pragma unroll
            for (int k = 0; k < 4; k++) {
                int j = lane + 32 * k;
                e[k] = (j < MBK) ? expf(v[k] - m) : 0.f;
                sum += e[k];
            }
            sum = warpsum(sum);
            float inv = 1.f / sum;
            float* P = (warp == 8) ? s.par : (warp == 9) ? s.pawa : s.pawm;
#pragma unroll
            for (int k = 0; k < 4; k++) { int j = lane + 32 * k; if (j < MBK) P[j] = e[k] * inv; }
        } else if (warp == 11) {
            if (lane == 0) {
                float l0 = __ldcg(&g_acc[ar3][100]) + s.bwp_s[0];
                float l1 = __ldcg(&g_acc[ar3][101]) + s.bwp_s[1];
                float l2 = __ldcg(&g_acc[ar3][102]) + s.bwp_s[2];
                float m = fmaxf(l0, fmaxf(l1, l2));
                float e0 = expf(l0 - m), e1 = expf(l1 - m), e2 = expf(l2 - m);
                float inv = 1.f / (e0 + e1 + e2);
                s.aw[0] = e0 * inv; s.aw[1] = e1 * inv; s.aw[2] = e2 * inv;
            }
        } else {
            for (int i = tid - 384; i < 1536; i += 128) s.sx[i] = __ldcg(&st_rd[i]);
            if (warp == 12 && lane < 8) {
                int k = lane & 3;
                if (lane < 4) s.pre_rha[k] = __ldcg(&g_pre_rha[(size_t)t * HS + c4 + k]);
                else          s.pre_rhm[k] = __ldcg(&g_pre_rhm[(size_t)t * HS + c4 + k]);
            }
        }
        __syncthreads();

        // ============ phase A2: r-dot + tagged publish; x-parts; mem update ============
        float xpart = 0.f;
        if (warp < 4) {
            // r-dot over OLD mem, publish tagged; then own x-part
            int col = warp; float acc = 0.f;
#pragma unroll
            for (int k = 0; k < 4; k++) {
                int j = lane + 32 * k;
                if (j < MBK) acc = fmaf(s.par[j], s.mem[mb][col][j], acc);
            }
            acc = warpsum(acc);
            if (lane == 0) {
                unsigned long long u = ((unsigned long long)want << 32)
                                     | (unsigned long long)__float_as_uint(acc);
                stcg_u64(&g_rt[c4 + col], u);
            }
            const float* w = s.wrh[col];
            const float* x = s.sx + 1024;
#pragma unroll
            for (int i = lane; i < 512; i += 32) xpart = fmaf(x[i], w[512 + i], xpart);
        } else if (warp < 12) {
            int mat = warp >> 2, col = warp & 3;
            const float* w = (mat == 1) ? s.wrha[col] : s.wrhm[col];
            const float* x = (mat == 1) ? s.sx : (s.sx + 512);
#pragma unroll
            for (int i = lane; i < 512; i += 32) xpart = fmaf(x[i], w[512 + i], xpart);
        } else {
            // mem update: read mem[mb], write mem[mb^1] (no WAR with r-dot)
            float aw0 = s.aw[0], aw1 = s.aw[1], aw2 = s.aw[2];
            for (int idx = tid - 384; idx < 4 * MBK; idx += 128) {
                int col = idx & 3, j = idx >> 2;
                s.mem[mb ^ 1][col][j] = fmaf(aw0, s.mem[mb][col][j],
                                        fmaf(aw1 * s.pawa[j], s.ca_own[col],
                                             aw2 * s.pawm[j] * s.cm_own[col]));
            }
        }

        // ============ phase B: tagged r gather + r-part dots + state publish ============
        if (warp < 12) {
            int mat = warp >> 2, col = warp & 3;
            const float* w = (mat == 0) ? s.wrh[col] : (mat == 1) ? s.wrha[col] : s.wrhm[col];
            unsigned long long u[16];
#pragma unroll
            for (int k = 0; k < 16; k++) u[k] = ldcg_u64(&g_rt[lane + 32 * k]);
            for (;;) {
                bool stale = false;
#pragma unroll
                for (int k = 0; k < 16; k++)
                    if ((unsigned)(u[k] >> 32) != want) stale = true;
                if (!stale) break;
#pragma unroll
                for (int k = 0; k < 16; k++)
                    if ((unsigned)(u[k] >> 32) != want) u[k] = ldcg_u64(&g_rt[lane + 32 * k]);
            }
            float acc = xpart;
#pragma unroll
            for (int k = 0; k < 16; k++)
                acc = fmaf(__uint_as_float((unsigned)u[k]), w[lane + 32 * k], acc);
            acc = warpsum(acc);
            if (lane == 0) {
                if (mat == 0) {
                    float h1 = fmaxf(acc + s.brh[col], 0.f);
                    s.snew[8 + col] = h1;
                    __stcg(&st_wr[1024 + c4 + col], h1);
                    out[(size_t)t * HS + c4 + col] = h1;
                } else if (mat == 1) {
                    float ha1 = fmaxf(acc + s.pre_rha[col], 0.f);
                    s.snew[col] = ha1;
                    __stcg(&st_wr[c4 + col], ha1);
                } else {
                    float hm1 = fmaxf(acc + s.pre_rhm[col], 0.f);
                    s.snew[4 + col] = hm1;
                    __stcg(&st_wr[512 + c4 + col], hm1);
                }
            }
        } else if (warp == 14 && lane < 4 && cta < 80) {
            // zero the acc buffer that will be pushed at t+1 (last read at t-1)
            __stcg(&g_acc[az3][c4 + lane], 0.f);
        }
        __syncthreads();

        // push partial logits for step t+1 (303 spread-address float REDs)
        if (t + 1 < T_STEPS && tid < 303) {
            float p = 0.f;
            int slot;
            if (tid < MBK) {
#pragma unroll
                for (int k = 0; k < 12; k++) p = fmaf(s.snew[k], s.wrp_r[k][tid], p);
                slot = tid;
            } else if (tid < MBK + 3) {
                int j = tid - MBK;
#pragma unroll
                for (int k = 0; k < 12; k++) p = fmaf(s.snew[k], s.wwp_r[k][j], p);
                slot = 100 + j;
            } else if (tid < 203) {
                int j = tid - 103;
#pragma unroll
                for (int k = 0; k < 4; k++) p = fmaf(s.snew[k], s.wwpa_r[k][j], p);
                slot = 103 + j;
            } else {
                int j = tid - 203;
#pragma unroll
                for (int k = 0; k < 4; k++) p = fmaf(s.snew[4 + k], s.wwpm_r[k][j], p);
                slot = 203 + j;
            }
            atomicAdd(&g_acc[ap3][slot], p);
        }
        // single end-of-step barrier
        gbar_arrive();
        gbar_wait((unsigned)(t + 1) * NCTA, &s.epoch);
    }
}

// =====================================================================
extern "C" void kernel_launch(void* const* d_in, const int* in_sizes, int n_in,
                              void* d_out, int out_size)
{
    const float* Xa    = (const float*)d_in[0];
    const float* Xm    = (const float*)d_in[1];
    const float* W_ca  = (const float*)d_in[2];
    const float* b_ca  = (const float*)d_in[3];
    const float* W_cm  = (const float*)d_in[4];
    const float* b_cm  = (const float*)d_in[5];
    const float* W_wp  = (const float*)d_in[6];
    const float* b_wp  = (const float*)d_in[7];
    const float* W_wpa = (const float*)d_in[8];
    const float* b_wpa = (const float*)d_in[9];
    const float* W_wpm = (const float*)d_in[10];
    const float* b_wpm = (const float*)d_in[11];
    const float* W_rp  = (const float*)d_in[12];
    const float* b_rp  = (const float*)d_in[13];
    const float* W_rh  = (const float*)d_in[14];
    const float* b_rh  = (const float*)d_in[15];
    const float* W_rha = (const float*)d_in[16];
    const float* W_rhm = (const float*)d_in[18];
    float* out = (float*)d_out;

    static bool attr_set = false;
    if (!attr_set) {
        cudaFuncSetAttribute(seq_kernel, cudaFuncAttributeMaxDynamicSharedMemorySize,
                             (int)sizeof(SeqSmem));
        attr_set = true;
    }

    dim3 ggrid(4, T_STEPS / 128, 6);
    gemm6_kernel<<<ggrid, 256>>>(Xa, Xm,
                                 W_rha, (const float*)d_in[17],
                                 W_rhm, (const float*)d_in[19],
                                 W_ca, b_ca, W_cm, b_cm,
                                 W_wpa, b_wpa, W_wpm, b_wpm);
    reset_kernel<<<8, 512>>>();
    seq_kernel<<<NCTA, NTHR, sizeof(SeqSmem)>>>(W_ca, W_cm, W_wp, b_wp, W_wpa, W_wpm,
                                                W_rp, b_rp, W_rh, b_rh, W_rha, W_rhm,
                                                out);
}

// round 15
// speedup vs baseline: 1.1850x; 1.1850x over previous
#include <cuda_runtime.h>
#include <cuda_bf16.h>
#include <math.h>
#include <stdint.h>

#define T_STEPS 4096
#define HS 512
#define INSZ 2048
#define MBK 100
#define NCTA 128
#define NTHR 512

#define BAR_SYNC(id, cnt)   asm volatile("bar.sync %0, %1;"   :: "r"(id), "r"(cnt) : "memory")
#define BAR_ARRIVE(id, cnt) asm volatile("bar.arrive %0, %1;" :: "r"(id), "r"(cnt) : "memory")

// ---------------- device scratch (allocations are forbidden) ----------------
__device__ float g_pre_rha[T_STEPS * HS];
__device__ float g_pre_rhm[T_STEPS * HS];
__device__ float g_pre_ca [T_STEPS * HS];
__device__ float g_pre_cm [T_STEPS * HS];
__device__ float g_pre_wpa[T_STEPS * MBK];
__device__ float g_pre_wpm[T_STEPS * MBK];
__device__ float g_state[2][3 * HS];       // double-buffered: [ha | hm | h]
__device__ float g_r[HS];
// logit accumulators, TRIPLE buffered: [0..99]=ar, [100..102]=aw,
// [103..202]=aw_a(ha part), [203..302]=aw_m(hm part)
__device__ float g_acc[3][320];
__device__ unsigned int g_bar1;            // r-ready counter (1 per CTA per step)
__device__ unsigned int g_bar2;            // end-of-step counter

__device__ __forceinline__ float warpsum(float v) {
#pragma unroll
    for (int o = 16; o; o >>= 1) v += __shfl_xor_sync(0xFFFFFFFFu, v, o);
    return v;
}

__device__ __forceinline__ unsigned int ld_acq(const unsigned int* p) {
    unsigned int v;
    asm volatile("ld.global.acquire.gpu.u32 %0, [%1];" : "=r"(v) : "l"(p));
    return v;
}

// end-of-step barrier (R13-proven): arrive = syncthreads + release-add;
// wait = warp 15 acquires global counter, publishes SMEM epoch; others spin SMEM.
__device__ __forceinline__ void gbar_arrive() {
    __syncthreads();
    if (threadIdx.x == 0)
        asm volatile("red.release.gpu.global.add.u32 [%0], 1;" :: "l"(&g_bar2) : "memory");
}
__device__ __forceinline__ void gbar_wait(unsigned int target, volatile unsigned int* epoch) {
    const int warp = threadIdx.x >> 5, lane = threadIdx.x & 31;
    if (warp == 15) {
        if (lane == 0) {
            while (ld_acq(&g_bar2) < target) {}
            *epoch = target;
        }
        __syncwarp();
    } else {
        if (lane == 0) { while (*epoch < target) {} }
        __syncwarp();
    }
}

__global__ void reset_kernel() {
    int i = blockIdx.x * blockDim.x + threadIdx.x;
    if (i == 0) { g_bar1 = 0u; g_bar2 = 0u; }
    if (i < 3 * 320) (&g_acc[0][0])[i] = 0.f;
    if (i < 2 * 3 * HS) (&g_state[0][0])[i] = 0.f;
    if (i < HS) g_r[i] = 0.f;
}

// =====================================================================
// Precompute GEMMs: C[4096,N] = X @ W[rowOff:+2048, :N] + bias (6 jobs in z)
// =====================================================================
__global__ __launch_bounds__(256)
void gemm6_kernel(const float* __restrict__ Xa, const float* __restrict__ Xm,
                  const float* __restrict__ W_rha, const float* __restrict__ b_rha,
                  const float* __restrict__ W_rhm, const float* __restrict__ b_rhm,
                  const float* __restrict__ W_ca,  const float* __restrict__ b_ca,
                  const float* __restrict__ W_cm,  const float* __restrict__ b_cm,
                  const float* __restrict__ W_wpa, const float* __restrict__ b_wpa,
                  const float* __restrict__ W_wpm, const float* __restrict__ b_wpm)
{
    const float* A; const float* B; const float* bias; float* C; int N; int rowOff;
    switch (blockIdx.z) {
        case 0: A = Xa; B = W_rha; bias = b_rha; C = g_pre_rha; N = HS;  rowOff = 0;   break;
        case 1: A = Xm; B = W_rhm; bias = b_rhm; C = g_pre_rhm; N = HS;  rowOff = 0;   break;
        case 2: A = Xa; B = W_ca;  bias = b_ca;  C = g_pre_ca;  N = HS;  rowOff = HS;  break;
        case 3: A = Xm; B = W_cm;  bias = b_cm;  C = g_pre_cm;  N = HS;  rowOff = HS;  break;
        case 4: A = Xa; B = W_wpa; bias = b_wpa; C = g_pre_wpa; N = MBK; rowOff = HS;  break;
        default:A = Xm; B = W_wpm; bias = b_wpm; C = g_pre_wpm; N = MBK; rowOff = HS;  break;
    }
    if ((int)blockIdx.x * 128 >= N) return;

    const int K = INSZ;
    __shared__ float As[8][128];
    __shared__ float Bs[8][128];
    const int tid  = threadIdx.x;
    const int tx   = tid & 15, ty = tid >> 4;
    const int brow = blockIdx.y, bcol = blockIdx.x;

    const int arow = tid >> 1, akq = (tid & 1) * 4;
    const float* Ag = A + (size_t)(brow * 128 + arow) * K + akq;
    const int bk = tid >> 5, bc = (tid & 31) * 4;
    const int gcol = bcol * 128 + bc;
    const bool bok = (gcol + 3 < N);

    float acc[8][8];
#pragma unroll
    for (int i = 0; i < 8; i++)
#pragma unroll
        for (int j = 0; j < 8; j++) acc[i][j] = 0.f;

    for (int k0 = 0; k0 < K; k0 += 8) {
        float4 av = *(const float4*)(Ag + k0);
        As[akq + 0][arow] = av.x; As[akq + 1][arow] = av.y;
        As[akq + 2][arow] = av.z; As[akq + 3][arow] = av.w;
        float4 bv = bok ? *(const float4*)(B + (size_t)(rowOff + k0 + bk) * N + gcol)
                        : make_float4(0.f, 0.f, 0.f, 0.f);
        *(float4*)&Bs[bk][bc] = bv;
        __syncthreads();
#pragma unroll
        for (int kk = 0; kk < 8; ++kk) {
            float ra[8], rb[8];
            *(float4*)(ra)     = *(const float4*)&As[kk][ty * 4];
            *(float4*)(ra + 4) = *(const float4*)&As[kk][64 + ty * 4];
            *(float4*)(rb)     = *(const float4*)&Bs[kk][tx * 4];
            *(float4*)(rb + 4) = *(const float4*)&Bs[kk][64 + tx * 4];
#pragma unroll
            for (int i = 0; i < 8; i++)
#pragma unroll
                for (int j = 0; j < 8; j++) acc[i][j] = fmaf(ra[i], rb[j], acc[i][j]);
        }
        __syncthreads();
    }
#pragma unroll
    for (int i = 0; i < 8; i++) {
        int row = brow * 128 + ((i < 4) ? (ty * 4 + i) : (64 + ty * 4 + i - 4));
#pragma unroll
        for (int j = 0; j < 8; j++) {
            int col = bcol * 128 + ((j < 4) ? (tx * 4 + j) : (64 + tx * 4 + j - 4));
            if (col < N) C[(size_t)row * N + col] = acc[i][j] + bias[col];
        }
    }
}

// =====================================================================
// Persistent sequential kernel: 128 CTAs x 512 threads, each owns 4 HS columns.
// Producer-gated r-round (hidden under x-part dots) + one end-of-step barrier.
// =====================================================================
struct SeqSmem {
    float wrh [4][1024];   // W_rh  col slices: rows [r(512) | h(512)]
    float wrha[4][1024];   // W_rha rows 2048..3071: [r | ha]
    float wrhm[4][1024];   // W_rhm rows 2048..3071: [r | hm]
    float wca [4][512];    // W_ca rows 0..511 (ha)
    float wcm [4][512];    // W_cm rows 0..511 (hm)
    float wrp_r [12][104]; // W_rp rows owned x 100 logits
    float wwp_r [12][4];   // W_wp rows owned x 3
    float wwpa_r[4][104];  // W_wpa rows c4..+3 (ha part) x 100
    float wwpm_r[4][104];
    float mem [2][4][MBK]; // DOUBLE-buffered mem[:, owned cols], col-major
    float par [MBK], pawa[MBK], pawm[MBK], aw[3];
    float snew[12];        // [ha1(4) | hm1(4) | h1(4)]
    float ca_own[4], cm_own[4];
    float brh[4];
    float brp_s[MBK], bwp_s[3];
    unsigned int repoch;   // r-ready epoch (published by warp 12)
    unsigned int epoch;    // end-of-step epoch (published by warp 15)
};

__global__ __launch_bounds__(NTHR, 1)
void seq_kernel(const float* __restrict__ W_ca,  const float* __restrict__ W_cm,
                const float* __restrict__ W_wp,  const float* __restrict__ b_wp,
                const float* __restrict__ W_wpa, const float* __restrict__ W_wpm,
                const float* __restrict__ W_rp,  const float* __restrict__ b_rp,
                const float* __restrict__ W_rh,  const float* __restrict__ b_rh,
                const float* __restrict__ W_rha, const float* __restrict__ W_rhm,
                float* __restrict__ out)
{
    extern __shared__ float smem_raw[];
    SeqSmem& s = *reinterpret_cast<SeqSmem*>(smem_raw);
    const int tid  = threadIdx.x;
    const int warp = tid >> 5, lane = tid & 31;
    const int cta  = blockIdx.x;
    const int c4   = cta * 4;

    // ---- one-time weight load ----
    for (int idx = tid; idx < 4 * 1024; idx += NTHR) {
        int col = idx & 3, i = idx >> 2;
        s.wrh [col][i] = __ldg(&W_rh [(size_t)i * HS + c4 + col]);
        s.wrha[col][i] = __ldg(&W_rha[(size_t)(INSZ + i) * HS + c4 + col]);
        s.wrhm[col][i] = __ldg(&W_rhm[(size_t)(INSZ + i) * HS + c4 + col]);
    }
    for (int idx = tid; idx < 4 * 512; idx += NTHR) {
        int col = idx & 3, i = idx >> 2;
        s.wca[col][i] = __ldg(&W_ca[(size_t)i * HS + c4 + col]);
        s.wcm[col][i] = __ldg(&W_cm[(size_t)i * HS + c4 + col]);
    }
    for (int idx = tid; idx < 12 * MBK; idx += NTHR) {
        int k = idx / MBK, j = idx % MBK;
        int row = (k < 4) ? (c4 + k) : (k < 8) ? (512 + c4 + k - 4) : (1024 + c4 + k - 8);
        s.wrp_r[k][j] = __ldg(&W_rp[(size_t)row * MBK + j]);
    }
    if (tid < 36) {
        int k = tid / 3, j = tid % 3;
        int row = (k < 4) ? (c4 + k) : (k < 8) ? (512 + c4 + k - 4) : (1024 + c4 + k - 8);
        s.wwp_r[k][j] = __ldg(&W_wp[(size_t)row * 3 + j]);
    }
    for (int idx = tid; idx < 4 * MBK; idx += NTHR) {
        int k = idx / MBK, j = idx % MBK;
        s.wwpa_r[k][j] = __ldg(&W_wpa[(size_t)(c4 + k) * MBK + j]);
        s.wwpm_r[k][j] = __ldg(&W_wpm[(size_t)(c4 + k) * MBK + j]);
    }
    for (int i = tid; i < MBK; i += NTHR) s.brp_s[i] = __ldg(&b_rp[i]);
    if (tid < 3) s.bwp_s[tid] = b_wp[tid];
    if (tid < 4) s.brh[tid] = b_rh[c4 + tid];
    for (int idx = tid; idx < 2 * 4 * MBK; idx += NTHR) (&s.mem[0][0][0])[idx] = 0.f;
    if (tid == 0) { s.repoch = 0u; s.epoch = 0u; }
    __syncthreads();

    for (int t = 0; t < T_STEPS; ++t) {
        const int mb  = t & 1;
        const int ar3 = t % 3, ap3 = (t + 1) % 3, az3 = (t + 2) % 3;
        const float* st_rd = g_state[t & 1];
        float*       st_wr = g_state[(t & 1) ^ 1];
        const unsigned want = (unsigned)(t + 1);

        float xpart = 0.f;
        float pre_own = 0.f;   // bias/pre for this warp's output (lane 0)

        if (warp < 4) {
            // ---- c_a dot → arrive(3); wait par via bar(2); r-dot; release g_bar1; xpart mat0 ----
            int col = warp;
            float pre = (lane == 0) ? __ldcg(&g_pre_ca[(size_t)t * HS + c4 + col]) : 0.f;
            float acc = 0.f;
#pragma unroll
            for (int i = 0; i < 512; i += 32)
                acc = fmaf(__ldcg(&st_rd[i + lane]), s.wca[col][i + lane], acc);
            acc = warpsum(acc);
            if (lane == 0) s.ca_own[col] = fmaxf(acc + pre, 0.f);
            BAR_ARRIVE(3, 480);
            BAR_SYNC(2, 160);                     // par ready (warp 8)
            float racc = 0.f;
#pragma unroll
            for (int k = 0; k < 4; k++) {
                int j = lane + 32 * k;
                if (j < MBK) racc = fmaf(s.par[j], s.mem[mb][col][j], racc);
            }
            racc = warpsum(racc);
            if (lane == 0) __stcg(&g_r[c4 + col], racc);
            BAR_SYNC(1, 128);                     // warps 0-3: all r stored
            if (tid == 0)
                asm volatile("red.release.gpu.global.add.u32 [%0], 1;" :: "l"(&g_bar1) : "memory");
            pre_own = s.brh[col];
            const float* w = s.wrh[col];
#pragma unroll
            for (int i = lane; i < 512; i += 32)
                xpart = fmaf(__ldcg(&st_rd[1024 + i]), w[512 + i], xpart);
        } else if (warp < 8) {
            // ---- c_m dot → arrive(3); xpart mat1 ----
            int col = warp - 4;
            float pre = (lane == 0) ? __ldcg(&g_pre_cm[(size_t)t * HS + c4 + col]) : 0.f;
            float acc = 0.f;
#pragma unroll
            for (int i = 0; i < 512; i += 32)
                acc = fmaf(__ldcg(&st_rd[512 + i + lane]), s.wcm[col][i + lane], acc);
            acc = warpsum(acc);
            if (lane == 0) s.cm_own[col] = fmaxf(acc + pre, 0.f);
            BAR_ARRIVE(3, 480);
            if (lane == 0) pre_own = __ldcg(&g_pre_rha[(size_t)t * HS + c4 + col]);
            const float* w = s.wrha[col];
#pragma unroll
            for (int i = lane; i < 512; i += 32)
                xpart = fmaf(__ldcg(&st_rd[i]), w[512 + i], xpart);
        } else if (warp == 8) {
            // ---- ar softmax → par; bar(2); xpart mat2 col0 ----
            float v[4];
#pragma unroll
            for (int k = 0; k < 4; k++) {
                int j = lane + 32 * k;
                v[k] = (j < MBK) ? (__ldcg(&g_acc[ar3][j]) + s.brp_s[j]) : -1e30f;
            }
            float m = fmaxf(fmaxf(v[0], v[1]), fmaxf(v[2], v[3]));
#pragma unroll
            for (int o = 16; o; o >>= 1) m = fmaxf(m, __shfl_xor_sync(0xFFFFFFFFu, m, o));
            float e[4], sum = 0.f;
#pragma unroll
            for (int k = 0; k < 4; k++) {
                int j = lane + 32 * k;
                e[k] = (j < MBK) ? expf(v[k] - m) : 0.f;
                sum += e[k];
            }
            sum = warpsum(sum);
            float inv = 1.f / sum;
#pragma unroll
            for (int k = 0; k < 4; k++) { int j = lane + 32 * k; if (j < MBK) s.par[j] = e[k] * inv; }
            BAR_SYNC(2, 160);
            if (lane == 0) pre_own = __ldcg(&g_pre_rhm[(size_t)t * HS + c4 + 0]);
            const float* w = s.wrhm[0];
#pragma unroll
            for (int i = lane; i < 512; i += 32)
                xpart = fmaf(__ldcg(&st_rd[512 + i]), w[512 + i], xpart);
        } else if (warp < 11) {
            // ---- pawa / pawm softmax → arrive(3); xpart mat2 col1/2 ----
            float v[4];
#pragma unroll
            for (int k = 0; k < 4; k++) {
                int j = lane + 32 * k;
                if (j < MBK) {
                    if (warp == 9) v[k] = __ldcg(&g_acc[ar3][103 + j]) + __ldcg(&g_pre_wpa[(size_t)t * MBK + j]);
                    else           v[k] = __ldcg(&g_acc[ar3][203 + j]) + __ldcg(&g_pre_wpm[(size_t)t * MBK + j]);
                } else v[k] = -1e30f;
            }
            float m = fmaxf(fmaxf(v[0], v[1]), fmaxf(v[2], v[3]));
#pragma unroll
            for (int o = 16; o; o >>= 1) m = fmaxf(m, __shfl_xor_sync(0xFFFFFFFFu, m, o));
            float e[4], sum = 0.f;
#pragma unroll
            for (int k = 0; k < 4; k++) {
                int j = lane + 32 * k;
                e[k] = (j < MBK) ? expf(v[k] - m) : 0.f;
                sum += e[k];
            }
            sum = warpsum(sum);
            float inv = 1.f / sum;
            float* P = (warp == 9) ? s.pawa : s.pawm;
#pragma unroll
            for (int k = 0; k < 4; k++) { int j = lane + 32 * k; if (j < MBK) P[j] = e[k] * inv; }
            BAR_ARRIVE(3, 480);
            int col = warp & 3;   // 1 or 2
            if (lane == 0) pre_own = __ldcg(&g_pre_rhm[(size_t)t * HS + c4 + col]);
            const float* w = s.wrhm[col];
#pragma unroll
            for (int i = lane; i < 512; i += 32)
                xpart = fmaf(__ldcg(&st_rd[512 + i]), w[512 + i], xpart);
        } else if (warp == 11) {
            // ---- aw gate → arrive(3); xpart mat2 col3 ----
            if (lane == 0) {
                float l0 = __ldcg(&g_acc[ar3][100]) + s.bwp_s[0];
                float l1 = __ldcg(&g_acc[ar3][101]) + s.bwp_s[1];
                float l2 = __ldcg(&g_acc[ar3][102]) + s.bwp_s[2];
                float m = fmaxf(l0, fmaxf(l1, l2));
                float e0 = expf(l0 - m), e1 = expf(l1 - m), e2 = expf(l2 - m);
                float inv = 1.f / (e0 + e1 + e2);
                s.aw[0] = e0 * inv; s.aw[1] = e1 * inv; s.aw[2] = e2 * inv;
            }
            BAR_ARRIVE(3, 480);
            if (lane == 0) pre_own = __ldcg(&g_pre_rhm[(size_t)t * HS + c4 + 3]);
            const float* w = s.wrhm[3];
#pragma unroll
            for (int i = lane; i < 512; i += 32)
                xpart = fmaf(__ldcg(&st_rd[512 + i]), w[512 + i], xpart);
        } else if (warp == 12) {
            // ---- poll r-ready, publish repoch; then join update via bar(3) ----
            if (lane == 0) {
                while (ld_acq(&g_bar1) < want * NCTA) {}
                *(volatile unsigned int*)&s.repoch = want;
            }
            __syncwarp();
            BAR_SYNC(3, 480);
            float aw0 = s.aw[0], aw1 = s.aw[1], aw2 = s.aw[2];
            for (int idx = tid - 384; idx < 4 * MBK; idx += 128) {
                int col = idx & 3, j = idx >> 2;
                s.mem[mb ^ 1][col][j] = fmaf(aw0, s.mem[mb][col][j],
                                        fmaf(aw1 * s.pawa[j], s.ca_own[col],
                                             aw2 * s.pawm[j] * s.cm_own[col]));
            }
        } else {
            // ---- warps 13-15: mem update (+ warp 14 zeroes acc buffer) ----
            BAR_SYNC(3, 480);
            float aw0 = s.aw[0], aw1 = s.aw[1], aw2 = s.aw[2];
            for (int idx = tid - 384; idx < 4 * MBK; idx += 128) {
                int col = idx & 3, j = idx >> 2;
                s.mem[mb ^ 1][col][j] = fmaf(aw0, s.mem[mb][col][j],
                                        fmaf(aw1 * s.pawa[j], s.ca_own[col],
                                             aw2 * s.pawm[j] * s.cm_own[col]));
            }
            if (warp == 14 && lane < 4 && cta < 80) __stcg(&g_acc[az3][c4 + lane], 0.f);
        }

        // ---- dot warps: wait r-ready (SMEM spin), finish dots ----
        if (warp < 12) {
            if (lane == 0) { while (*(volatile unsigned int*)&s.repoch < want) {} }
            __syncwarp();
            int mat = warp >> 2, col = warp & 3;
            const float* w = (mat == 0) ? s.wrh[col] : (mat == 1) ? s.wrha[col] : s.wrhm[col];
            float acc = xpart;
#pragma unroll
            for (int k = 0; k < 16; k++)
                acc = fmaf(__ldcg(&g_r[lane + 32 * k]), w[lane + 32 * k], acc);
            acc = warpsum(acc);
            if (lane == 0) {
                if (mat == 0) {
                    float h1 = fmaxf(acc + pre_own, 0.f);
                    s.snew[8 + col] = h1;
                    __stcg(&st_wr[1024 + c4 + col], h1);
                    out[(size_t)t * HS + c4 + col] = h1;
                } else if (mat == 1) {
                    float ha1 = fmaxf(acc + pre_own, 0.f);
                    s.snew[col] = ha1;
                    __stcg(&st_wr[c4 + col], ha1);
                } else {
                    float hm1 = fmaxf(acc + pre_own, 0.f);
                    s.snew[4 + col] = hm1;
                    __stcg(&st_wr[512 + c4 + col], hm1);
                }
            }
        }
        __syncthreads();

        // ---- push partial logits for step t+1 (303 spread-address float REDs) ----
        if (t + 1 < T_STEPS && tid < 303) {
            float p = 0.f;
            int slot;
            if (tid < MBK) {
#pragma unroll
                for (int k = 0; k < 12; k++) p = fmaf(s.snew[k], s.wrp_r[k][tid], p);
                slot = tid;
            } else if (tid < MBK + 3) {
                int j = tid - MBK;
#pragma unroll
                for (int k = 0; k < 12; k++) p = fmaf(s.snew[k], s.wwp_r[k][j], p);
                slot = 100 + j;
            } else if (tid < 203) {
                int j = tid - 103;
#pragma unroll
                for (int k = 0; k < 4; k++) p = fmaf(s.snew[k], s.wwpa_r[k][j], p);
                slot = 103 + j;
            } else {
                int j = tid - 203;
#pragma unroll
                for (int k = 0; k < 4; k++) p = fmaf(s.snew[4 + k], s.wwpm_r[k][j], p);
                slot = 203 + j;
            }
            atomicAdd(&g_acc[ap3][slot], p);
        }
        // ---- single end-of-step global barrier ----
        gbar_arrive();
        gbar_wait(want * NCTA, &s.epoch);
    }
}

// =====================================================================
extern "C" void kernel_launch(void* const* d_in, const int* in_sizes, int n_in,
                              void* d_out, int out_size)
{
    const float* Xa    = (const float*)d_in[0];
    const float* Xm    = (const float*)d_in[1];
    const float* W_ca  = (const float*)d_in[2];
    const float* b_ca  = (const float*)d_in[3];
    const float* W_cm  = (const float*)d_in[4];
    const float* b_cm  = (const float*)d_in[5];
    const float* W_wp  = (const float*)d_in[6];
    const float* b_wp  = (const float*)d_in[7];
    const float* W_wpa = (const float*)d_in[8];
    const float* b_wpa = (const float*)d_in[9];
    const float* W_wpm = (const float*)d_in[10];
    const float* b_wpm = (const float*)d_in[11];
    const float* W_rp  = (const float*)d_in[12];
    const float* b_rp  = (const float*)d_in[13];
    const float* W_rh  = (const float*)d_in[14];
    const float* b_rh  = (const float*)d_in[15];
    const float* W_rha = (const float*)d_in[16];
    const float* W_rhm = (const float*)d_in[18];
    float* out = (float*)d_out;

    static bool attr_set = false;
    if (!attr_set) {
        cudaFuncSetAttribute(seq_kernel, cudaFuncAttributeMaxDynamicSharedMemorySize,
                             (int)sizeof(SeqSmem));
        attr_set = true;
    }

    dim3 ggrid(4, T_STEPS / 128, 6);
    gemm6_kernel<<<ggrid, 256>>>(Xa, Xm,
                                 W_rha, (const float*)d_in[17],
                                 W_rhm, (const float*)d_in[19],
                                 W_ca, b_ca, W_cm, b_cm,
                                 W_wpa, b_wpa, W_wpm, b_wpm);
    reset_kernel<<<8, 512>>>();
    seq_kernel<<<NCTA, NTHR, sizeof(SeqSmem)>>>(W_ca, W_cm, W_wp, b_wp, W_wpa, W_wpm,
                                                W_rp, b_rp, W_rh, b_rh, W_rha, W_rhm,
                                                out);
}

// round 16
// speedup vs baseline: 1.2241x; 1.0329x over previous
#include <cuda_runtime.h>
#include <cuda_bf16.h>
#include <math.h>
#include <stdint.h>

#define T_STEPS 4096
#define HS 512
#define INSZ 2048
#define MBK 100
#define NCTA 128
#define NTHR 512

#define BAR_SYNC(id, cnt) asm volatile("bar.sync %0, %1;" :: "r"(id), "r"(cnt) : "memory")

// ---------------- device scratch (allocations are forbidden) ----------------
__device__ float g_pre_rha[T_STEPS * HS];
__device__ float g_pre_rhm[T_STEPS * HS];
__device__ float g_pre_ca [T_STEPS * HS];
__device__ float g_pre_cm [T_STEPS * HS];
__device__ float g_pre_wpa[T_STEPS * MBK];
__device__ float g_pre_wpm[T_STEPS * MBK];
__device__ float g_state[2][3 * HS];       // double-buffered: [ha | hm | h]
__device__ float g_r[HS];
// logit accumulators, TRIPLE buffered: [0..99]=ar, [100..102]=aw,
// [103..202]=aw_a(ha part), [203..302]=aw_m(hm part)
__device__ float g_acc[3][320];
__device__ unsigned int g_bar1;            // r-ready counter (1 per CTA per step)
__device__ unsigned int g_bar2;            // end-of-step counter

__device__ __forceinline__ float warpsum(float v) {
#pragma unroll
    for (int o = 16; o; o >>= 1) v += __shfl_xor_sync(0xFFFFFFFFu, v, o);
    return v;
}

__device__ __forceinline__ unsigned int ld_acq(const unsigned int* p) {
    unsigned int v;
    asm volatile("ld.global.acquire.gpu.u32 %0, [%1];" : "=r"(v) : "l"(p));
    return v;
}

// end-of-step barrier (R13-proven)
__device__ __forceinline__ void gbar_arrive() {
    __syncthreads();
    if (threadIdx.x == 0)
        asm volatile("red.release.gpu.global.add.u32 [%0], 1;" :: "l"(&g_bar2) : "memory");
}
__device__ __forceinline__ void gbar_wait(unsigned int target, volatile unsigned int* epoch) {
    const int warp = threadIdx.x >> 5, lane = threadIdx.x & 31;
    if (warp == 15) {
        if (lane == 0) {
            while (ld_acq(&g_bar2) < target) {}
            *epoch = target;
        }
        __syncwarp();
    } else {
        if (lane == 0) { while (*epoch < target) {} }
        __syncwarp();
    }
}

__global__ void reset_kernel() {
    int i = blockIdx.x * blockDim.x + threadIdx.x;
    if (i == 0) { g_bar1 = 0u; g_bar2 = 0u; }
    if (i < 3 * 320) (&g_acc[0][0])[i] = 0.f;
    if (i < 2 * 3 * HS) (&g_state[0][0])[i] = 0.f;
    if (i < HS) g_r[i] = 0.f;
}

// =====================================================================
// Precompute GEMMs: C[4096,N] = X @ W[rowOff:+2048, :N] + bias (6 jobs in z)
// =====================================================================
__global__ __launch_bounds__(256)
void gemm6_kernel(const float* __restrict__ Xa, const float* __restrict__ Xm,
                  const float* __restrict__ W_rha, const float* __restrict__ b_rha,
                  const float* __restrict__ W_rhm, const float* __restrict__ b_rhm,
                  const float* __restrict__ W_ca,  const float* __restrict__ b_ca,
                  const float* __restrict__ W_cm,  const float* __restrict__ b_cm,
                  const float* __restrict__ W_wpa, const float* __restrict__ b_wpa,
                  const float* __restrict__ W_wpm, const float* __restrict__ b_wpm)
{
    const float* A; const float* B; const float* bias; float* C; int N; int rowOff;
    switch (blockIdx.z) {
        case 0: A = Xa; B = W_rha; bias = b_rha; C = g_pre_rha; N = HS;  rowOff = 0;   break;
        case 1: A = Xm; B = W_rhm; bias = b_rhm; C = g_pre_rhm; N = HS;  rowOff = 0;   break;
        case 2: A = Xa; B = W_ca;  bias = b_ca;  C = g_pre_ca;  N = HS;  rowOff = HS;  break;
        case 3: A = Xm; B = W_cm;  bias = b_cm;  C = g_pre_cm;  N = HS;  rowOff = HS;  break;
        case 4: A = Xa; B = W_wpa; bias = b_wpa; C = g_pre_wpa; N = MBK; rowOff = HS;  break;
        default:A = Xm; B = W_wpm; bias = b_wpm; C = g_pre_wpm; N = MBK; rowOff = HS;  break;
    }
    if ((int)blockIdx.x * 128 >= N) return;

    const int K = INSZ;
    __shared__ float As[8][128];
    __shared__ float Bs[8][128];
    const int tid  = threadIdx.x;
    const int tx   = tid & 15, ty = tid >> 4;
    const int brow = blockIdx.y, bcol = blockIdx.x;

    const int arow = tid >> 1, akq = (tid & 1) * 4;
    const float* Ag = A + (size_t)(brow * 128 + arow) * K + akq;
    const int bk = tid >> 5, bc = (tid & 31) * 4;
    const int gcol = bcol * 128 + bc;
    const bool bok = (gcol + 3 < N);

    float acc[8][8];
#pragma unroll
    for (int i = 0; i < 8; i++)
#pragma unroll
        for (int j = 0; j < 8; j++) acc[i][j] = 0.f;

    for (int k0 = 0; k0 < K; k0 += 8) {
        float4 av = *(const float4*)(Ag + k0);
        As[akq + 0][arow] = av.x; As[akq + 1][arow] = av.y;
        As[akq + 2][arow] = av.z; As[akq + 3][arow] = av.w;
        float4 bv = bok ? *(const float4*)(B + (size_t)(rowOff + k0 + bk) * N + gcol)
                        : make_float4(0.f, 0.f, 0.f, 0.f);
        *(float4*)&Bs[bk][bc] = bv;
        __syncthreads();
#pragma unroll
        for (int kk = 0; kk < 8; ++kk) {
            float ra[8], rb[8];
            *(float4*)(ra)     = *(const float4*)&As[kk][ty * 4];
            *(float4*)(ra + 4) = *(const float4*)&As[kk][64 + ty * 4];
            *(float4*)(rb)     = *(const float4*)&Bs[kk][tx * 4];
            *(float4*)(rb + 4) = *(const float4*)&Bs[kk][64 + tx * 4];
#pragma unroll
            for (int i = 0; i < 8; i++)
#pragma unroll
                for (int j = 0; j < 8; j++) acc[i][j] = fmaf(ra[i], rb[j], acc[i][j]);
        }
        __syncthreads();
    }
#pragma unroll
    for (int i = 0; i < 8; i++) {
        int row = brow * 128 + ((i < 4) ? (ty * 4 + i) : (64 + ty * 4 + i - 4));
#pragma unroll
        for (int j = 0; j < 8; j++) {
            int col = bcol * 128 + ((j < 4) ? (tx * 4 + j) : (64 + tx * 4 + j - 4));
            if (col < N) C[(size_t)row * N + col] = acc[i][j] + bias[col];
        }
    }
}

// =====================================================================
// Persistent sequential kernel: 128 CTAs x 512 threads, each owns 4 HS columns.
// Self-contained warp-8 r-chain + r-ready counter; one end-of-step barrier.
// =====================================================================
struct SeqSmem {
    float wrh [4][1024];   // W_rh  col slices: rows [r(512) | h(512)]
    float wrha[4][1024];   // W_rha rows 2048..3071: [r | ha]
    float wrhm[4][1024];   // W_rhm rows 2048..3071: [r | hm]
    float wca [4][512];    // W_ca rows 0..511 (ha)
    float wcm [4][512];    // W_cm rows 0..511 (hm)
    float wrp_r [12][104]; // W_rp rows owned x 100 logits
    float wwp_r [12][4];   // W_wp rows owned x 3
    float wwpa_r[4][104];  // W_wpa rows c4..+3 (ha part) x 100
    float wwpm_r[4][104];
    float mem [2][4][MBK]; // DOUBLE-buffered mem[:, owned cols], col-major
    float sx  [1536];      // state staged for x-part dots
    float pawa[MBK], pawm[MBK], aw[3];
    float snew[12];        // [ha1(4) | hm1(4) | h1(4)]
    float ca_own[4], cm_own[4];
    float pre_rha[4], pre_rhm[4];
    float brh[4];
    float brp_s[MBK], bwp_s[3];
    unsigned int repoch;   // r-ready epoch (published by warp 15)
    unsigned int epoch;    // end-of-step epoch (published by warp 15)
};

__global__ __launch_bounds__(NTHR, 1)
void seq_kernel(const float* __restrict__ W_ca,  const float* __restrict__ W_cm,
                const float* __restrict__ W_wp,  const float* __restrict__ b_wp,
                const float* __restrict__ W_wpa, const float* __restrict__ W_wpm,
                const float* __restrict__ W_rp,  const float* __restrict__ b_rp,
                const float* __restrict__ W_rh,  const float* __restrict__ b_rh,
                const float* __restrict__ W_rha, const float* __restrict__ W_rhm,
                float* __restrict__ out)
{
    extern __shared__ float smem_raw[];
    SeqSmem& s = *reinterpret_cast<SeqSmem*>(smem_raw);
    const int tid  = threadIdx.x;
    const int warp = tid >> 5, lane = tid & 31;
    const int cta  = blockIdx.x;
    const int c4   = cta * 4;

    // ---- one-time weight load ----
    for (int idx = tid; idx < 4 * 1024; idx += NTHR) {
        int col = idx & 3, i = idx >> 2;
        s.wrh [col][i] = __ldg(&W_rh [(size_t)i * HS + c4 + col]);
        s.wrha[col][i] = __ldg(&W_rha[(size_t)(INSZ + i) * HS + c4 + col]);
        s.wrhm[col][i] = __ldg(&W_rhm[(size_t)(INSZ + i) * HS + c4 + col]);
    }
    for (int idx = tid; idx < 4 * 512; idx += NTHR) {
        int col = idx & 3, i = idx >> 2;
        s.wca[col][i] = __ldg(&W_ca[(size_t)i * HS + c4 + col]);
        s.wcm[col][i] = __ldg(&W_cm[(size_t)i * HS + c4 + col]);
    }
    for (int idx = tid; idx < 12 * MBK; idx += NTHR) {
        int k = idx / MBK, j = idx % MBK;
        int row = (k < 4) ? (c4 + k) : (k < 8) ? (512 + c4 + k - 4) : (1024 + c4 + k - 8);
        s.wrp_r[k][j] = __ldg(&W_rp[(size_t)row * MBK + j]);
    }
    if (tid < 36) {
        int k = tid / 3, j = tid % 3;
        int row = (k < 4) ? (c4 + k) : (k < 8) ? (512 + c4 + k - 4) : (1024 + c4 + k - 8);
        s.wwp_r[k][j] = __ldg(&W_wp[(size_t)row * 3 + j]);
    }
    for (int idx = tid; idx < 4 * MBK; idx += NTHR) {
        int k = idx / MBK, j = idx % MBK;
        s.wwpa_r[k][j] = __ldg(&W_wpa[(size_t)(c4 + k) * MBK + j]);
        s.wwpm_r[k][j] = __ldg(&W_wpm[(size_t)(c4 + k) * MBK + j]);
    }
    for (int i = tid; i < MBK; i += NTHR) s.brp_s[i] = __ldg(&b_rp[i]);
    if (tid < 3) s.bwp_s[tid] = b_wp[tid];
    if (tid < 4) s.brh[tid] = b_rh[c4 + tid];
    for (int idx = tid; idx < 2 * 4 * MBK; idx += NTHR) (&s.mem[0][0][0])[idx] = 0.f;
    if (tid == 0) { s.repoch = 0u; s.epoch = 0u; }
    __syncthreads();

    for (int t = 0; t < T_STEPS; ++t) {
        const int mb  = t & 1;
        const int ar3 = t % 3, ap3 = (t + 1) % 3, az3 = (t + 2) % 3;
        const float* st_rd = g_state[t & 1];
        float*       st_wr = g_state[(t & 1) ^ 1];
        const unsigned want = (unsigned)(t + 1);

        float xpart = 0.f;
        float pre_own = 0.f;

        if (warp == 8) {
            // ===== self-contained r-chain: logits -> softmax -> r -> release =====
            float v[4];
#pragma unroll
            for (int k = 0; k < 4; k++) {
                int j = lane + 32 * k;
                v[k] = (j < MBK) ? (__ldcg(&g_acc[ar3][j]) + s.brp_s[j]) : -1e30f;
            }
            float m = fmaxf(fmaxf(v[0], v[1]), fmaxf(v[2], v[3]));
#pragma unroll
            for (int o = 16; o; o >>= 1) m = fmaxf(m, __shfl_xor_sync(0xFFFFFFFFu, m, o));
            float e[4], sum = 0.f;
#pragma unroll
            for (int k = 0; k < 4; k++) {
                int j = lane + 32 * k;
                e[k] = (j < MBK) ? expf(v[k] - m) : 0.f;
                sum += e[k];
            }
            sum = warpsum(sum);
            float inv = 1.f / sum;
#pragma unroll
            for (int k = 0; k < 4; k++) e[k] *= inv;   // par in registers
#pragma unroll
            for (int col = 0; col < 4; col++) {
                float racc = 0.f;
#pragma unroll
                for (int k = 0; k < 4; k++) {
                    int j = lane + 32 * k;
                    if (j < MBK) racc = fmaf(e[k], s.mem[mb][col][j], racc);
                }
                racc = warpsum(racc);
                if (lane == 0) __stcg(&g_r[c4 + col], racc);
            }
            __syncwarp();
            if (lane == 0)
                asm volatile("red.release.gpu.global.add.u32 [%0], 1;" :: "l"(&g_bar1) : "memory");
            // own x-part (mat2 col0) directly from L2 (avoids bar(3) dependence)
            if (lane == 0) pre_own = __ldcg(&g_pre_rhm[(size_t)t * HS + c4 + 0]);
            const float* w = s.wrhm[0];
#pragma unroll
            for (int i = lane; i < 512; i += 32)
                xpart = fmaf(__ldcg(&st_rd[512 + i]), w[512 + i], xpart);
        } else if (warp < 8) {
            // ===== c_a (0-3) / c_m (4-7) dots =====
            int col = warp & 3;
            bool isA = warp < 4;
            float pre = 0.f;
            if (lane == 0)
                pre = __ldcg(isA ? &g_pre_ca[(size_t)t * HS + c4 + col]
                                 : &g_pre_cm[(size_t)t * HS + c4 + col]);
            const float* w  = isA ? s.wca[col] : s.wcm[col];
            const float* xg = isA ? st_rd : (st_rd + 512);
            float acc = 0.f;
#pragma unroll
            for (int i = 0; i < 512; i += 32) acc = fmaf(__ldcg(&xg[i + lane]), w[i + lane], acc);
            acc = warpsum(acc);
            if (lane == 0) {
                if (isA) s.ca_own[col] = fmaxf(acc + pre, 0.f);
                else     s.cm_own[col] = fmaxf(acc + pre, 0.f);
            }
            BAR_SYNC(3, 448);
            int mat = warp >> 2;   // 0 or 1
            pre_own = (mat == 0) ? s.brh[col] : s.pre_rha[col];
            const float* wx = (mat == 0) ? s.wrh[col] : s.wrha[col];
            const float* x  = (mat == 0) ? (s.sx + 1024) : s.sx;
#pragma unroll
            for (int i = lane; i < 512; i += 32) xpart = fmaf(x[i], wx[512 + i], xpart);
        } else if (warp < 11) {
            // ===== pawa (9) / pawm (10) softmaxes =====
            float v[4];
#pragma unroll
            for (int k = 0; k < 4; k++) {
                int j = lane + 32 * k;
                if (j < MBK) {
                    if (warp == 9) v[k] = __ldcg(&g_acc[ar3][103 + j]) + __ldcg(&g_pre_wpa[(size_t)t * MBK + j]);
                    else           v[k] = __ldcg(&g_acc[ar3][203 + j]) + __ldcg(&g_pre_wpm[(size_t)t * MBK + j]);
                } else v[k] = -1e30f;
            }
            float m = fmaxf(fmaxf(v[0], v[1]), fmaxf(v[2], v[3]));
#pragma unroll
            for (int o = 16; o; o >>= 1) m = fmaxf(m, __shfl_xor_sync(0xFFFFFFFFu, m, o));
            float e[4], sum = 0.f;
#pragma unroll
            for (int k = 0; k < 4; k++) {
                int j = lane + 32 * k;
                e[k] = (j < MBK) ? expf(v[k] - m) : 0.f;
                sum += e[k];
            }
            sum = warpsum(sum);
            float inv = 1.f / sum;
            float* P = (warp == 9) ? s.pawa : s.pawm;
#pragma unroll
            for (int k = 0; k < 4; k++) { int j = lane + 32 * k; if (j < MBK) P[j] = e[k] * inv; }
            BAR_SYNC(3, 448);
            int col = warp - 8;    // 1 or 2
            pre_own = s.pre_rhm[col];
            const float* wx = s.wrhm[col];
#pragma unroll
            for (int i = lane; i < 512; i += 32) xpart = fmaf(s.sx[512 + i], wx[512 + i], xpart);
        } else if (warp == 11) {
            // ===== aw gate =====
            if (lane == 0) {
                float l0 = __ldcg(&g_acc[ar3][100]) + s.bwp_s[0];
                float l1 = __ldcg(&g_acc[ar3][101]) + s.bwp_s[1];
                float l2 = __ldcg(&g_acc[ar3][102]) + s.bwp_s[2];
                float m = fmaxf(l0, fmaxf(l1, l2));
                float e0 = expf(l0 - m), e1 = expf(l1 - m), e2 = expf(l2 - m);
                float inv = 1.f / (e0 + e1 + e2);
                s.aw[0] = e0 * inv; s.aw[1] = e1 * inv; s.aw[2] = e2 * inv;
            }
            BAR_SYNC(3, 448);
            pre_own = s.pre_rhm[3];
            const float* wx = s.wrhm[3];
#pragma unroll
            for (int i = lane; i < 512; i += 32) xpart = fmaf(s.sx[512 + i], wx[512 + i], xpart);
        } else if (warp < 15) {
            // ===== warps 12-14: stage sx, then mem update =====
            for (int i = tid - 384; i < 1536; i += 96) s.sx[i] = __ldcg(&st_rd[i]);
            if (warp == 12 && lane < 8) {
                int k = lane & 3;
                if (lane < 4) s.pre_rha[k] = __ldcg(&g_pre_rha[(size_t)t * HS + c4 + k]);
                else          s.pre_rhm[k] = __ldcg(&g_pre_rhm[(size_t)t * HS + c4 + k]);
            }
            BAR_SYNC(3, 448);
            float aw0 = s.aw[0], aw1 = s.aw[1], aw2 = s.aw[2];
            for (int idx = tid - 384; idx < 4 * MBK; idx += 96) {
                int col = idx & 3, j = idx >> 2;
                s.mem[mb ^ 1][col][j] = fmaf(aw0, s.mem[mb][col][j],
                                        fmaf(aw1 * s.pawa[j], s.ca_own[col],
                                             aw2 * s.pawm[j] * s.cm_own[col]));
            }
            if (warp == 14 && lane < 4 && cta < 80) __stcg(&g_acc[az3][c4 + lane], 0.f);
        } else {
            // ===== warp 15: poll r-ready, publish repoch =====
            if (lane == 0) {
                while (ld_acq(&g_bar1) < want * NCTA) {}
                *(volatile unsigned int*)&s.repoch = want;
            }
            __syncwarp();
        }

        // ---- dot warps: wait r-ready (SMEM spin), finish with direct g_r reads ----
        if (warp < 12) {
            if (lane == 0) { while (*(volatile unsigned int*)&s.repoch < want) {} }
            __syncwarp();
            int mat = warp >> 2, col = warp & 3;
            const float* w = (mat == 0) ? s.wrh[col] : (mat == 1) ? s.wrha[col] : s.wrhm[col];
            float acc = xpart;
#pragma unroll
            for (int k = 0; k < 16; k++)
                acc = fmaf(__ldcg(&g_r[lane + 32 * k]), w[lane + 32 * k], acc);
            acc = warpsum(acc);
            if (lane == 0) {
                if (mat == 0) {
                    float h1 = fmaxf(acc + pre_own, 0.f);
                    s.snew[8 + col] = h1;
                    __stcg(&st_wr[1024 + c4 + col], h1);
                    out[(size_t)t * HS + c4 + col] = h1;
                } else if (mat == 1) {
                    float ha1 = fmaxf(acc + pre_own, 0.f);
                    s.snew[col] = ha1;
                    __stcg(&st_wr[c4 + col], ha1);
                } else {
                    float hm1 = fmaxf(acc + pre_own, 0.f);
                    s.snew[4 + col] = hm1;
                    __stcg(&st_wr[512 + c4 + col], hm1);
                }
            }
        }
        __syncthreads();

        // ---- push partial logits for step t+1 (303 spread-address float REDs) ----
        if (t + 1 < T_STEPS && tid < 303) {
            float p = 0.f;
            int slot;
            if (tid < MBK) {
#pragma unroll
                for (int k = 0; k < 12; k++) p = fmaf(s.snew[k], s.wrp_r[k][tid], p);
                slot = tid;
            } else if (tid < MBK + 3) {
                int j = tid - MBK;
#pragma unroll
                for (int k = 0; k < 12; k++) p = fmaf(s.snew[k], s.wwp_r[k][j], p);
                slot = 100 + j;
            } else if (tid < 203) {
                int j = tid - 103;
#pragma unroll
                for (int k = 0; k < 4; k++) p = fmaf(s.snew[k], s.wwpa_r[k][j], p);
                slot = 103 + j;
            } else {
                int j = tid - 203;
#pragma unroll
                for (int k = 0; k < 4; k++) p = fmaf(s.snew[4 + k], s.wwpm_r[k][j], p);
                slot = 203 + j;
            }
            atomicAdd(&g_acc[ap3][slot], p);
        }
        // ---- single end-of-step global barrier ----
        gbar_arrive();
        gbar_wait(want * NCTA, &s.epoch);
    }
}

// =====================================================================
extern "C" void kernel_launch(void* const* d_in, const int* in_sizes, int n_in,
                              void* d_out, int out_size)
{
    const float* Xa    = (const float*)d_in[0];
    const float* Xm    = (const float*)d_in[1];
    const float* W_ca  = (const float*)d_in[2];
    const float* b_ca  = (const float*)d_in[3];
    const float* W_cm  = (const float*)d_in[4];
    const float* b_cm  = (const float*)d_in[5];
    const float* W_wp  = (const float*)d_in[6];
    const float* b_wp  = (const float*)d_in[7];
    const float* W_wpa = (const float*)d_in[8];
    const float* b_wpa = (const float*)d_in[9];
    const float* W_wpm = (const float*)d_in[10];
    const float* b_wpm = (const float*)d_in[11];
    const float* W_rp  = (const float*)d_in[12];
    const float* b_rp  = (const float*)d_in[13];
    const float* W_rh  = (const float*)d_in[14];
    const float* b_rh  = (const float*)d_in[15];
    const float* W_rha = (const float*)d_in[16];
    const float* W_rhm = (const float*)d_in[18];
    float* out = (float*)d_out;

    static bool attr_set = false;
    if (!attr_set) {
        cudaFuncSetAttribute(seq_kernel, cudaFuncAttributeMaxDynamicSharedMemorySize,
                             (int)sizeof(SeqSmem));
        attr_set = true;
    }

    dim3 ggrid(4, T_STEPS / 128, 6);
    gemm6_kernel<<<ggrid, 256>>>(Xa, Xm,
                                 W_rha, (const float*)d_in[17],
                                 W_rhm, (const float*)d_in[19],
                                 W_ca, b_ca, W_cm, b_cm,
                                 W_wpa, b_wpa, W_wpm, b_wpm);
    reset_kernel<<<8, 512>>>();
    seq_kernel<<<NCTA, NTHR, sizeof(SeqSmem)>>>(W_ca, W_cm, W_wp, b_wp, W_wpa, W_wpm,
                                                W_rp, b_rp, W_rh, b_rh, W_rha, W_rhm,
                                                out);
}